// round 12
// baseline (speedup 1.0000x reference)
#include <cuda_runtime.h>
#include <cstdint>

#define BATCH 8
#define CH    512
#define PIX   4096            // 64*64
#define CP    (CH*PIX)        // 2,097,152
#define TOT   (BATCH*CP)      // 16,777,216

// Scratch (device globals: allocation-free per harness rules)
__device__ float  g_f[2][TOT];      // conv outputs f_opt / f_sar
__device__ float  g_S[2][TOT];      // Gram matrices S_opt / S_sar
__device__ float4 g_red[BATCH*PIX]; // per-(b,pixel): (m1, z1, m2, z2)

// ---------------------------------------------------------------------------
// tf32 helpers
// ---------------------------------------------------------------------------
__device__ __forceinline__ float tf32r(float x) {
    uint32_t u; asm("cvt.rna.tf32.f32 %0, %1;" : "=r"(u) : "f"(x));
    return __uint_as_float(u);
}
// m16n8k8 tf32 mma (sm_80 baseline PTX -> HMMA; legal on plain sm_103)
__device__ __forceinline__ void mma1688(float* c, const uint32_t* a, const uint32_t* b) {
    asm volatile(
        "mma.sync.aligned.m16n8k8.row.col.f32.tf32.tf32.f32 "
        "{%0,%1,%2,%3}, {%4,%5,%6,%7}, {%8,%9}, {%0,%1,%2,%3};"
        : "+f"(c[0]), "+f"(c[1]), "+f"(c[2]), "+f"(c[3])
        : "r"(a[0]), "r"(a[1]), "r"(a[2]), "r"(a[3]), "r"(b[0]), "r"(b[1]));
}

// ---------------------------------------------------------------------------
// Kernel A: 1x1 conv as tf32 tensor-core GEMM with 3xTF32 compensation.
// (R10 structure; B fragments now loaded inside the j-loop to cut live regs.)
// ---------------------------------------------------------------------------
#define APLANE 2112                 // 16 groups * 132 floats
#define BPLANE 2112                 // 32 groups * 66 floats
#define SLABF  (2*APLANE + 2*BPLANE)  // 8448 floats per buffer
#define CONV_SMEM (2*SLABF*4)       // 67584 bytes

__global__ __launch_bounds__(256)
void conv_mma(const float* __restrict__ opt, const float* __restrict__ sar,
              const float* __restrict__ Wopt, const float* __restrict__ Wsar)
{
    extern __shared__ float sm[];

    const int t    = threadIdx.x;
    const int w    = t >> 5;
    const int lane = t & 31;
    const int g    = lane >> 2;       // 0..7
    const int tg   = lane & 3;        // 0..3

    const int branch = blockIdx.z >> 3;
    const int batch  = blockIdx.z & 7;
    const float* __restrict__ Wm = branch ? Wsar : Wopt;
    const float* __restrict__ X  = (branch ? sar : opt) + (size_t)batch * CP;
    float* __restrict__ F = g_f[branch] + (size_t)batch * CP;

    const int m_base = blockIdx.y * 128;
    const int n_base = blockIdx.x * 128;

    // ---- staging coordinates ----
    const int s_mt = t >> 5;
    const float* Wr1 = Wm + (size_t)(m_base + s_mt * 16 + g) * CH;
    const float* Wr2 = Wr1 + (size_t)8 * CH;
    const int aAdr0 = (0 * 8 + s_mt) * 132 + lane * 4;   // half 0
    const int aAdr1 = (1 * 8 + s_mt) * 132 + lane * 4;   // half 1
    const int brow  = t >> 4;
    const int bntile = t & 15;
    const float* Xp = X + (size_t)brow * PIX + n_base + bntile * 8;
    const int bhalf = brow >> 3, r8 = brow & 7;
    const int bpair = r8 >> 2,  btg = r8 & 3;
    const int bFragBase = (bhalf * 16 + bntile) * 66 + btg * 2 + bpair;

    // ---- compute coordinates ----
    const int wm = w >> 2;            // 0..1  (64-row half)
    const int wn = w & 3;             // 0..3  (32-col strip)

    float acc[4][4][4];
    #pragma unroll
    for (int i = 0; i < 4; i++)
        #pragma unroll
        for (int j = 0; j < 4; j++)
            #pragma unroll
            for (int q = 0; q < 4; q++) acc[i][j][q] = 0.f;

    float  aR[2][4];
    float4 bR[2];

    auto ldSlab = [&](int k0) {
        #pragma unroll
        for (int h = 0; h < 2; h++) {
            const int kb = k0 + h * 8;
            aR[h][0] = Wr1[kb + tg];
            aR[h][1] = Wr2[kb + tg];
            aR[h][2] = Wr1[kb + tg + 4];
            aR[h][3] = Wr2[kb + tg + 4];
        }
        bR[0] = *(const float4*)(Xp + (size_t)k0 * PIX);
        bR[1] = *(const float4*)(Xp + (size_t)k0 * PIX + 4);
    };
    auto stage = [&](int buf) {
        float* base = sm + buf * SLABF;
        float* aHi = base;
        float* aLo = base + APLANE;
        float* bHi = base + 2 * APLANE;
        float* bLo = base + 2 * APLANE + BPLANE;
        #pragma unroll
        for (int h = 0; h < 2; h++) {
            float hi[4], lo[4];
            #pragma unroll
            for (int q = 0; q < 4; q++) {
                hi[q] = tf32r(aR[h][q]);
                lo[q] = tf32r(aR[h][q] - hi[q]);
            }
            const int adr = h ? aAdr1 : aAdr0;
            *(float4*)&aHi[adr] = make_float4(hi[0], hi[1], hi[2], hi[3]);
            *(float4*)&aLo[adr] = make_float4(lo[0], lo[1], lo[2], lo[3]);
        }
        float bv[8] = {bR[0].x, bR[0].y, bR[0].z, bR[0].w,
                       bR[1].x, bR[1].y, bR[1].z, bR[1].w};
        #pragma unroll
        for (int j = 0; j < 8; j++) {
            float hi = tf32r(bv[j]);
            float lo = tf32r(bv[j] - hi);
            bHi[bFragBase + j * 8] = hi;
            bLo[bFragBase + j * 8] = lo;
        }
    };
    auto compute = [&](int buf) {
        const float* base = sm + buf * SLABF;
        #pragma unroll
        for (int h = 0; h < 2; h++) {
            uint32_t aH[4][4], aL[4][4];
            #pragma unroll
            for (int i = 0; i < 4; i++) {
                const int adr = (h * 8 + wm * 4 + i) * 132 + lane * 4;
                *(uint4*)aH[i] = *(const uint4*)&base[adr];
                *(uint4*)aL[i] = *(const uint4*)&base[APLANE + adr];
            }
            #pragma unroll
            for (int j = 0; j < 4; j++) {
                const int adr = (h * 16 + wn * 4 + j) * 66 + lane * 2;
                uint32_t bH[2], bL[2];
                *(uint2*)bH = *(const uint2*)&base[2 * APLANE + adr];
                *(uint2*)bL = *(const uint2*)&base[2 * APLANE + BPLANE + adr];
                #pragma unroll
                for (int i = 0; i < 4; i++) {
                    mma1688(acc[i][j], aH[i], bH);
                    mma1688(acc[i][j], aH[i], bL);
                    mma1688(acc[i][j], aL[i], bH);
                }
            }
        }
    };

    ldSlab(0);
    stage(0);
    __syncthreads();

    for (int it = 0; it < 32; ++it) {
        const int buf = it & 1;
        if (it < 31) ldSlab((it + 1) * 16);
        compute(buf);
        if (it < 31) {
            stage(buf ^ 1);
            __syncthreads();
        }
    }

    #pragma unroll
    for (int i = 0; i < 4; i++) {
        const int row0 = m_base + wm * 64 + i * 16 + g;
        #pragma unroll
        for (int j = 0; j < 4; j++) {
            const int col = n_base + wn * 32 + j * 8 + 2 * tg;
            *(float2*)&F[(size_t)row0 * PIX + col] =
                make_float2(acc[i][j][0], acc[i][j][1]);
            *(float2*)&F[(size_t)(row0 + 8) * PIX + col] =
                make_float2(acc[i][j][2], acc[i][j][3]);
        }
    }
}

// ---------------------------------------------------------------------------
// Kernel B: per-(b,c) Gram S = f^T f (64x64x64) on tensor cores, 3xTF32.
// One CTA (256 thr) per bc, both branches.  Since A = f^T and B = f, the
// m16n8k8 A-fragment of mtile m equals the B-fragments of ntiles 2m/2m+1 at
// the same lane -> ONE fragment-major smem layout serves both operands.
// Layout per branch: hi plane then lo plane; plane = 64 groups (k8*8+ntile)
// of 66 floats; lane l holds [b0,b1]=f[k8*8+tg(+4)][n*8+g] at offset l*2.
// Warp w: branch = w>>2, mtile = w&3; 8 ntiles x 8 ksteps x 3 = 192 HMMA.
// ---------------------------------------------------------------------------
#define AT_PLANE 4224                 // 64 groups * 66 floats
#define AT_BR    (2*AT_PLANE)         // hi + lo
#define ATTN_SMEM (2*AT_BR*4)         // 67584 bytes

__global__ __launch_bounds__(256)
void attn_mma()
{
    extern __shared__ float sm[];
    const int bc = blockIdx.x;                   // 0..4095 = b*512+c
    const int t  = threadIdx.x;

    // ---- staging: g_f -> hi/lo fragment-major smem (both branches) ----
    const float4* gsrc[2] = {
        (const float4*)(g_f[0] + (size_t)bc * PIX),
        (const float4*)(g_f[1] + (size_t)bc * PIX) };
    #pragma unroll
    for (int q = 0; q < 4; q++) {
        const int fid = t + 256 * q;             // float4 id within branch
        const int h   = fid >> 4;                // 0..63
        const int i0  = (fid & 15) * 4;          // 0..60
        const int k8 = h >> 3, tgh = h & 3, pair = (h >> 2) & 1;
        #pragma unroll
        for (int br = 0; br < 2; br++) {
            float4 v = gsrc[br][fid];
            float vv[4] = {v.x, v.y, v.z, v.w};
            #pragma unroll
            for (int e = 0; e < 4; e++) {
                const int i  = i0 + e;
                const int n  = i >> 3, gg = i & 7;
                const int off = br * AT_BR + (k8 * 8 + n) * 66
                              + (gg * 4 + tgh) * 2 + pair;
                float hi = tf32r(vv[e]);
                sm[off]            = hi;
                sm[off + AT_PLANE] = tf32r(vv[e] - hi);
            }
        }
    }
    __syncthreads();

    // ---- compute ----
    const int w = t >> 5, lane = t & 31;
    const int br = w >> 2, m = w & 3;
    const float* base = sm + br * AT_BR;

    float acc[8][4];
    #pragma unroll
    for (int j = 0; j < 8; j++)
        #pragma unroll
        for (int q = 0; q < 4; q++) acc[j][q] = 0.f;

    #pragma unroll
    for (int k = 0; k < 8; k++) {
        uint2 h0 = *(const uint2*)&base[(k * 8 + 2 * m)     * 66 + lane * 2];
        uint2 h1 = *(const uint2*)&base[(k * 8 + 2 * m + 1) * 66 + lane * 2];
        uint2 l0 = *(const uint2*)&base[AT_PLANE + (k * 8 + 2 * m)     * 66 + lane * 2];
        uint2 l1 = *(const uint2*)&base[AT_PLANE + (k * 8 + 2 * m + 1) * 66 + lane * 2];
        uint32_t aH[4] = {h0.x, h1.x, h0.y, h1.y};
        uint32_t aL[4] = {l0.x, l1.x, l0.y, l1.y};
        #pragma unroll
        for (int j = 0; j < 8; j++) {
            uint32_t bH[2], bL[2];
            *(uint2*)bH = *(const uint2*)&base[(k * 8 + j) * 66 + lane * 2];
            *(uint2*)bL = *(const uint2*)&base[AT_PLANE + (k * 8 + j) * 66 + lane * 2];
            mma1688(acc[j], aH, bH);
            mma1688(acc[j], aH, bL);
            mma1688(acc[j], aL, bH);
        }
    }

    // ---- epilogue ----
    const int g = lane >> 2, tg = lane & 3;
    float* S = g_S[br] + (size_t)bc * PIX;
    #pragma unroll
    for (int j = 0; j < 8; j++) {
        const int col = j * 8 + 2 * tg;
        *(float2*)&S[(m * 16 + g) * 64 + col]     = make_float2(acc[j][0], acc[j][1]);
        *(float2*)&S[(m * 16 + g + 8) * 64 + col] = make_float2(acc[j][2], acc[j][3]);
    }
}

// ---------------------------------------------------------------------------
// Kernel C: softmax statistics, two-pass (max pass has no exp; sum pass has
// exactly one exp per element -> half the MUFU work of the online form).
// ---------------------------------------------------------------------------
__global__ __launch_bounds__(256)
void softmax_stats()
{
    const int p = blockIdx.x * 256 + threadIdx.x;   // 0..4095
    const int b = blockIdx.y;
    const float* __restrict__ s1 = g_S[0] + (size_t)b * CP + p;
    const float* __restrict__ s2 = g_S[1] + (size_t)b * CP + p;

    float m1 = -3.4e38f, m2 = -3.4e38f;
    #pragma unroll 8
    for (int c = 0; c < CH; ++c) {
        m1 = fmaxf(m1, s1[c * PIX]);
        m2 = fmaxf(m2, s2[c * PIX]);
    }
    float z1 = 0.f, z2 = 0.f;
    #pragma unroll 8
    for (int c = 0; c < CH; ++c) {
        z1 += __expf(s1[c * PIX] - m1);
        z2 += __expf(s2[c * PIX] - m2);
    }
    g_red[b * PIX + p] = make_float4(m1, z1, m2, z2);
}

// ---------------------------------------------------------------------------
// Kernel D: Att = f1*f2 * exp(2*((s1-m1)+(s2-m2))) / (z1*z2)^2
// ---------------------------------------------------------------------------
__global__ __launch_bounds__(256)
void finalize(float* __restrict__ out)
{
    const int e = blockIdx.x * 256 + threadIdx.x;
    const int b = e >> 21;          // / (CH*PIX)
    const int p = e & (PIX - 1);
    float4 r = g_red[(b << 12) + p];
    float s1 = g_S[0][e];
    float s2 = g_S[1][e];
    float f1 = g_f[0][e];
    float f2 = g_f[1][e];
    float rz = 1.0f / (r.y * r.w);
    float ex = __expf(2.0f * ((s1 - r.x) + (s2 - r.z)));
    out[e] = (f1 * f2) * (ex * rz * rz);
}

// ---------------------------------------------------------------------------
extern "C" void kernel_launch(void* const* d_in, const int* in_sizes, int n_in,
                              void* d_out, int out_size)
{
    const float* opt  = (const float*)d_in[0];
    const float* sar  = (const float*)d_in[1];
    const float* Wopt = (const float*)d_in[2];
    const float* Wsar = (const float*)d_in[3];
    float* out = (float*)d_out;

    cudaFuncSetAttribute(conv_mma, cudaFuncAttributeMaxDynamicSharedMemorySize,
                         CONV_SMEM);
    cudaFuncSetAttribute(attn_mma, cudaFuncAttributeMaxDynamicSharedMemorySize,
                         ATTN_SMEM);

    conv_mma<<<dim3(32, 4, 16), 256, CONV_SMEM>>>(opt, sar, Wopt, Wsar);
    attn_mma<<<dim3(4096, 1, 1), 256, ATTN_SMEM>>>();
    softmax_stats<<<dim3(16, 8), 256>>>();
    finalize<<<TOT / 256, 256>>>(out);
}

// round 14
// speedup vs baseline: 1.0391x; 1.0391x over previous
#include <cuda_runtime.h>
#include <cstdint>

#define BATCH 8
#define CH    512
#define PIX   4096            // 64*64
#define CP    (CH*PIX)        // 2,097,152
#define TOT   (BATCH*CP)      // 16,777,216

// Scratch (device globals: allocation-free per harness rules)
__device__ float  g_f[2][TOT];      // conv outputs f_opt / f_sar
__device__ float  g_S[2][TOT];      // Gram matrices S_opt / S_sar
__device__ float4 g_red[BATCH*PIX]; // per-(b,pixel): (m1, z1, m2, z2)

// ---------------------------------------------------------------------------
// tf32 helpers
// ---------------------------------------------------------------------------
__device__ __forceinline__ float tf32r(float x) {
    uint32_t u; asm("cvt.rna.tf32.f32 %0, %1;" : "=r"(u) : "f"(x));
    return __uint_as_float(u);
}
// m16n8k8 tf32 mma (sm_80 baseline PTX -> HMMA; legal on plain sm_103)
__device__ __forceinline__ void mma1688(float* c, const uint32_t* a, const uint32_t* b) {
    asm volatile(
        "mma.sync.aligned.m16n8k8.row.col.f32.tf32.tf32.f32 "
        "{%0,%1,%2,%3}, {%4,%5,%6,%7}, {%8,%9}, {%0,%1,%2,%3};"
        : "+f"(c[0]), "+f"(c[1]), "+f"(c[2]), "+f"(c[3])
        : "r"(a[0]), "r"(a[1]), "r"(a[2]), "r"(a[3]), "r"(b[0]), "r"(b[1]));
}

// ---------------------------------------------------------------------------
// Kernel A: 1x1 conv as tf32 tensor-core GEMM with 3xTF32 compensation.
// (R10 version, verbatim — known-good 821.7us baseline.)
// ---------------------------------------------------------------------------
#define APLANE 2112                 // 16 groups * 132 floats
#define BPLANE 2112                 // 32 groups * 66 floats
#define SLABF  (2*APLANE + 2*BPLANE)  // 8448 floats per buffer
#define CONV_SMEM (2*SLABF*4)       // 67584 bytes

__global__ __launch_bounds__(256)
void conv_mma(const float* __restrict__ opt, const float* __restrict__ sar,
              const float* __restrict__ Wopt, const float* __restrict__ Wsar)
{
    extern __shared__ float sm[];

    const int t    = threadIdx.x;
    const int w    = t >> 5;
    const int lane = t & 31;
    const int g    = lane >> 2;       // 0..7
    const int tg   = lane & 3;        // 0..3

    const int branch = blockIdx.z >> 3;
    const int batch  = blockIdx.z & 7;
    const float* __restrict__ Wm = branch ? Wsar : Wopt;
    const float* __restrict__ X  = (branch ? sar : opt) + (size_t)batch * CP;
    float* __restrict__ F = g_f[branch] + (size_t)batch * CP;

    const int m_base = blockIdx.y * 128;
    const int n_base = blockIdx.x * 128;

    // ---- staging coordinates ----
    const int s_mt = t >> 5;
    const float* Wr1 = Wm + (size_t)(m_base + s_mt * 16 + g) * CH;
    const float* Wr2 = Wr1 + (size_t)8 * CH;
    const int aAdr0 = (0 * 8 + s_mt) * 132 + lane * 4;   // half 0
    const int aAdr1 = (1 * 8 + s_mt) * 132 + lane * 4;   // half 1
    const int brow  = t >> 4;
    const int bntile = t & 15;
    const float* Xp = X + (size_t)brow * PIX + n_base + bntile * 8;
    const int bhalf = brow >> 3, r8 = brow & 7;
    const int bpair = r8 >> 2,  btg = r8 & 3;
    const int bFragBase = (bhalf * 16 + bntile) * 66 + btg * 2 + bpair;

    // ---- compute coordinates ----
    const int wm = w >> 2;            // 0..1  (64-row half)
    const int wn = w & 3;             // 0..3  (32-col strip)

    float acc[4][4][4];
    #pragma unroll
    for (int i = 0; i < 4; i++)
        #pragma unroll
        for (int j = 0; j < 4; j++)
            #pragma unroll
            for (int q = 0; q < 4; q++) acc[i][j][q] = 0.f;

    float  aR[2][4];
    float4 bR[2];

    auto ldSlab = [&](int k0) {
        #pragma unroll
        for (int h = 0; h < 2; h++) {
            const int kb = k0 + h * 8;
            aR[h][0] = Wr1[kb + tg];
            aR[h][1] = Wr2[kb + tg];
            aR[h][2] = Wr1[kb + tg + 4];
            aR[h][3] = Wr2[kb + tg + 4];
        }
        bR[0] = *(const float4*)(Xp + (size_t)k0 * PIX);
        bR[1] = *(const float4*)(Xp + (size_t)k0 * PIX + 4);
    };
    auto stage = [&](int buf) {
        float* base = sm + buf * SLABF;
        float* aHi = base;
        float* aLo = base + APLANE;
        float* bHi = base + 2 * APLANE;
        float* bLo = base + 2 * APLANE + BPLANE;
        #pragma unroll
        for (int h = 0; h < 2; h++) {
            float hi[4], lo[4];
            #pragma unroll
            for (int q = 0; q < 4; q++) {
                hi[q] = tf32r(aR[h][q]);
                lo[q] = tf32r(aR[h][q] - hi[q]);
            }
            const int adr = h ? aAdr1 : aAdr0;
            *(float4*)&aHi[adr] = make_float4(hi[0], hi[1], hi[2], hi[3]);
            *(float4*)&aLo[adr] = make_float4(lo[0], lo[1], lo[2], lo[3]);
        }
        float bv[8] = {bR[0].x, bR[0].y, bR[0].z, bR[0].w,
                       bR[1].x, bR[1].y, bR[1].z, bR[1].w};
        #pragma unroll
        for (int j = 0; j < 8; j++) {
            float hi = tf32r(bv[j]);
            float lo = tf32r(bv[j] - hi);
            bHi[bFragBase + j * 8] = hi;
            bLo[bFragBase + j * 8] = lo;
        }
    };
    auto compute = [&](int buf) {
        const float* base = sm + buf * SLABF;
        #pragma unroll
        for (int h = 0; h < 2; h++) {
            uint32_t aH[4][4], aL[4][4], bH[4][2], bL[4][2];
            #pragma unroll
            for (int i = 0; i < 4; i++) {
                const int adr = (h * 8 + wm * 4 + i) * 132 + lane * 4;
                *(uint4*)aH[i] = *(const uint4*)&base[adr];
                *(uint4*)aL[i] = *(const uint4*)&base[APLANE + adr];
            }
            #pragma unroll
            for (int j = 0; j < 4; j++) {
                const int adr = (h * 16 + wn * 4 + j) * 66 + lane * 2;
                *(uint2*)bH[j] = *(const uint2*)&base[2 * APLANE + adr];
                *(uint2*)bL[j] = *(const uint2*)&base[2 * APLANE + BPLANE + adr];
            }
            #pragma unroll
            for (int i = 0; i < 4; i++)
                #pragma unroll
                for (int j = 0; j < 4; j++) {
                    mma1688(acc[i][j], aH[i], bH[j]);
                    mma1688(acc[i][j], aH[i], bL[j]);
                    mma1688(acc[i][j], aL[i], bH[j]);
                }
        }
    };

    ldSlab(0);
    stage(0);
    __syncthreads();

    for (int it = 0; it < 32; ++it) {
        const int buf = it & 1;
        if (it < 31) ldSlab((it + 1) * 16);
        compute(buf);
        if (it < 31) {
            stage(buf ^ 1);
            __syncthreads();
        }
    }

    #pragma unroll
    for (int i = 0; i < 4; i++) {
        const int row0 = m_base + wm * 64 + i * 16 + g;
        #pragma unroll
        for (int j = 0; j < 4; j++) {
            const int col = n_base + wn * 32 + j * 8 + 2 * tg;
            *(float2*)&F[(size_t)row0 * PIX + col] =
                make_float2(acc[i][j][0], acc[i][j][1]);
            *(float2*)&F[(size_t)(row0 + 8) * PIX + col] =
                make_float2(acc[i][j][2], acc[i][j][3]);
        }
    }
}

// ---------------------------------------------------------------------------
// Kernel B: per-(b,c) Gram S = f^T f (64x64x64) on tensor cores, 3xTF32,
// fragments loaded DIRECTLY from gmem (no smem, no syncthreads).
// Fragment element (i,k): A[i][k] = f[k][i] -> fp[k*64 + i]; each LDG.32's
// 32 lanes touch 4 rows x 32B = 4 sectors (full efficiency). The 32KB
// f tile (both branches) is L1-resident, so cross-warp B redundancy is free.
// 8 warps: branch = w>>2, mtile = w&3; per warp 8 k-steps x 8 ntiles x 3 MMA.
// ---------------------------------------------------------------------------
__global__ __launch_bounds__(256)
void attn_mma()
{
    const int bc = blockIdx.x;                   // 0..4095 = b*512+c
    const int t  = threadIdx.x;
    const int w  = t >> 5, lane = t & 31;
    const int g  = lane >> 2, tg = lane & 3;
    const int br = w >> 2, m = w & 3;

    const float* __restrict__ fp = g_f[br] + (size_t)bc * PIX;

    float acc[8][4];
    #pragma unroll
    for (int j = 0; j < 8; j++)
        #pragma unroll
        for (int q = 0; q < 4; q++) acc[j][q] = 0.f;

    #pragma unroll
    for (int k = 0; k < 8; k++) {
        const float* r0 = fp + (8 * k + tg) * 64;        // k-row tg
        const float* r4 = r0 + 4 * 64;                   // k-row tg+4
        // A fragment: rows 16m+g(+8), k-cols tg(+4)
        float a0 = r0[16 * m + g];
        float a1 = r0[16 * m + g + 8];
        float a2 = r4[16 * m + g];
        float a3 = r4[16 * m + g + 8];
        uint32_t aH[4], aL[4];
        {
            float h0 = tf32r(a0), h1 = tf32r(a1), h2 = tf32r(a2), h3 = tf32r(a3);
            aH[0] = __float_as_uint(h0); aL[0] = __float_as_uint(tf32r(a0 - h0));
            aH[1] = __float_as_uint(h1); aL[1] = __float_as_uint(tf32r(a1 - h1));
            aH[2] = __float_as_uint(h2); aL[2] = __float_as_uint(tf32r(a2 - h2));
            aH[3] = __float_as_uint(h3); aL[3] = __float_as_uint(tf32r(a3 - h3));
        }
        #pragma unroll
        for (int j = 0; j < 8; j++) {
            float b0 = r0[8 * j + g];
            float b1 = r4[8 * j + g];
            uint32_t bH[2], bL[2];
            float h0 = tf32r(b0), h1 = tf32r(b1);
            bH[0] = __float_as_uint(h0); bL[0] = __float_as_uint(tf32r(b0 - h0));
            bH[1] = __float_as_uint(h1); bL[1] = __float_as_uint(tf32r(b1 - h1));
            mma1688(acc[j], aH, bH);
            mma1688(acc[j], aH, bL);
            mma1688(acc[j], aL, bH);
        }
    }

    float* S = g_S[br] + (size_t)bc * PIX;
    #pragma unroll
    for (int j = 0; j < 8; j++) {
        const int col = j * 8 + 2 * tg;
        *(float2*)&S[(m * 16 + g) * 64 + col]     = make_float2(acc[j][0], acc[j][1]);
        *(float2*)&S[(m * 16 + g + 8) * 64 + col] = make_float2(acc[j][2], acc[j][3]);
    }
}

// ---------------------------------------------------------------------------
// Kernel C: online softmax statistics over channel dim for both branches.
// (R10 version — part of the 821.7us baseline.)
// ---------------------------------------------------------------------------
__global__ __launch_bounds__(256)
void softmax_stats()
{
    const int p = blockIdx.x * 256 + threadIdx.x;   // 0..4095
    const int b = blockIdx.y;
    const float* __restrict__ s1 = g_S[0] + (size_t)b * CP + p;
    const float* __restrict__ s2 = g_S[1] + (size_t)b * CP + p;

    float m1 = -3.4e38f, z1 = 0.f;
    float m2 = -3.4e38f, z2 = 0.f;
    #pragma unroll 8
    for (int c = 0; c < CH; ++c) {
        float v1 = s1[c * PIX];
        float v2 = s2[c * PIX];
        float nm1 = fmaxf(m1, v1);
        z1 = z1 * __expf(m1 - nm1) + __expf(v1 - nm1);
        m1 = nm1;
        float nm2 = fmaxf(m2, v2);
        z2 = z2 * __expf(m2 - nm2) + __expf(v2 - nm2);
        m2 = nm2;
    }
    g_red[b * PIX + p] = make_float4(m1, z1, m2, z2);
}

// ---------------------------------------------------------------------------
// Kernel D: Att = f1*f2 * exp(2*((s1-m1)+(s2-m2))) / (z1*z2)^2
// ---------------------------------------------------------------------------
__global__ __launch_bounds__(256)
void finalize(float* __restrict__ out)
{
    const int e = blockIdx.x * 256 + threadIdx.x;
    const int b = e >> 21;          // / (CH*PIX)
    const int p = e & (PIX - 1);
    float4 r = g_red[(b << 12) + p];
    float s1 = g_S[0][e];
    float s2 = g_S[1][e];
    float f1 = g_f[0][e];
    float f2 = g_f[1][e];
    float rz = 1.0f / (r.y * r.w);
    float ex = __expf(2.0f * ((s1 - r.x) + (s2 - r.z)));
    out[e] = (f1 * f2) * (ex * rz * rz);
}

// ---------------------------------------------------------------------------
extern "C" void kernel_launch(void* const* d_in, const int* in_sizes, int n_in,
                              void* d_out, int out_size)
{
    const float* opt  = (const float*)d_in[0];
    const float* sar  = (const float*)d_in[1];
    const float* Wopt = (const float*)d_in[2];
    const float* Wsar = (const float*)d_in[3];
    float* out = (float*)d_out;

    cudaFuncSetAttribute(conv_mma, cudaFuncAttributeMaxDynamicSharedMemorySize,
                         CONV_SMEM);

    conv_mma<<<dim3(32, 4, 16), 256, CONV_SMEM>>>(opt, sar, Wopt, Wsar);
    attn_mma<<<dim3(4096, 1, 1), 256>>>();
    softmax_stats<<<dim3(16, 8), 256>>>();
    finalize<<<TOT / 256, 256>>>(out);
}